// round 14
// baseline (speedup 1.0000x reference)
#include <cuda_runtime.h>
#include <cuda_bf16.h>

#define F_EPS  1e-6f
#define F_TMAX 0.999f

struct V3 { float x, y, z; };

__device__ __forceinline__ V3 v3(float x, float y, float z) { V3 r; r.x=x; r.y=y; r.z=z; return r; }
__device__ __forceinline__ V3 vsub(V3 a, V3 b) { return v3(a.x-b.x, a.y-b.y, a.z-b.z); }
__device__ __forceinline__ V3 vadd(V3 a, V3 b) { return v3(a.x+b.x, a.y+b.y, a.z+b.z); }
__device__ __forceinline__ V3 vscale(V3 a, float s) { return v3(a.x*s, a.y*s, a.z*s); }
__device__ __forceinline__ float vdot(V3 a, V3 b) { return a.x*b.x + a.y*b.y + a.z*b.z; }
__device__ __forceinline__ V3 vcross(V3 a, V3 b) {
    return v3(a.y*b.z - a.z*b.y,
              a.z*b.x - a.x*b.z,
              a.x*b.y - a.y*b.x);
}
__device__ __forceinline__ V3 ldg3(const float* p) { return v3(__ldg(p), __ldg(p+1), __ldg(p+2)); }

__device__ __forceinline__ bool tri_contains(V3 a, V3 b, V3 c, V3 p) {
    V3 n0 = vcross(vsub(p, a), vsub(b, a));
    V3 n1 = vcross(vsub(p, b), vsub(c, b));
    V3 n2 = vcross(vsub(p, c), vsub(a, c));
    float d01 = vdot(n0, n1);
    float d12 = vdot(n1, n2);
    float d20 = vdot(n2, n0);
    bool pos = (d01 >= 0.f) && (d12 >= 0.f) && (d20 >= 0.f);
    bool neg = (d01 <= 0.f) && (d12 <= 0.f) && (d20 <= 0.f);
    return pos || neg;
}

// Survivor worklist (device globals — no runtime allocation).
#define LIST_CAP (1 << 16)
__device__ int g_count;
__device__ int g_list[LIST_CAP];

// ---------------- Kernel 1: image method + masks, push survivors ----------------
__global__ void __launch_bounds__(128) paths_kernel(
    const float* __restrict__ tx_g,      // [ntx,3]
    const float* __restrict__ rx_g,      // [nrx,3]
    const float* __restrict__ verts,     // [V,3]
    const float* __restrict__ normals,   // [T,3]
    const int*   __restrict__ tris,      // [T,3]
    const int*   __restrict__ pc,        // [P,2]
    float*       __restrict__ out,       // [P,ntx,nrx,4,3]
    int P, int T, int ntx, int nrx)
{
    int idx = blockIdx.x * blockDim.x + threadIdx.x;
    int pr  = ntx * nrx;
    long total = (long)P * pr;
    if (idx >= total) return;

    int p   = idx / pr;
    int rem = idx - p * pr;
    int it  = rem / nrx;
    int ir  = rem - it * nrx;

    V3 tx = ldg3(tx_g + 3*it);
    V3 rx = ldg3(rx_g + 3*ir);

    int m0 = __ldg(pc + 2*p + 0);
    int m1 = __ldg(pc + 2*p + 1);

    int ia0 = __ldg(tris + 3*m0 + 0), ib0 = __ldg(tris + 3*m0 + 1), ic0 = __ldg(tris + 3*m0 + 2);
    int ia1 = __ldg(tris + 3*m1 + 0), ib1 = __ldg(tris + 3*m1 + 1), ic1 = __ldg(tris + 3*m1 + 2);

    V3 A0 = ldg3(verts + 3*ia0), B0 = ldg3(verts + 3*ib0), C0 = ldg3(verts + 3*ic0);
    V3 A1 = ldg3(verts + 3*ia1), B1 = ldg3(verts + 3*ib1), C1 = ldg3(verts + 3*ic1);
    V3 n0 = ldg3(normals + 3*m0);
    V3 n1 = ldg3(normals + 3*m1);
    V3 v0 = A0;   // mirror_v = triangle vertex 0
    V3 v1 = A1;

    // ---- image method (order 2) ----
    V3 img0 = vsub(tx,   vscale(n0, 2.f * vdot(vsub(tx,   v0), n0)));
    V3 img1 = vsub(img0, vscale(n1, 2.f * vdot(vsub(img0, v1), n1)));

    V3 d1 = vsub(rx, img1);
    float den1 = vdot(d1, n1);
    den1 = (fabsf(den1) < F_EPS) ? F_EPS : den1;
    float t1 = vdot(vsub(v1, img1), n1) / den1;
    V3 p1 = vadd(img1, vscale(d1, t1));

    V3 d0 = vsub(p1, img0);
    float den0 = vdot(d0, n0);
    den0 = (fabsf(den0) < F_EPS) ? F_EPS : den0;
    float t0 = vdot(vsub(v0, img0), n0) / den0;
    V3 p0 = vadd(img0, vscale(d0, t0));

    // ---- containment + same-side masks ----
    bool mask = tri_contains(A0, B0, C0, p0) && tri_contains(A1, B1, C1, p1);
    if (mask) {
        float dp0 = vdot(vsub(tx, v0), n0);
        float dn0 = vdot(vsub(p1, v0), n0);
        float dp1 = vdot(vsub(p0, v1), n1);
        float dn1 = vdot(vsub(rx, v1), n1);
        mask = (dp0 * dn0 >= 0.f) && (dp1 * dn1 >= 0.f);
    }

    // ---- write tentative result; occlusion kernel zeroes the occluded ones ----
    float f[12];
    if (mask) {
        f[0] = tx.x; f[1]  = tx.y; f[2]  = tx.z;
        f[3] = p0.x; f[4]  = p0.y; f[5]  = p0.z;
        f[6] = p1.x; f[7]  = p1.y; f[8]  = p1.z;
        f[9] = rx.x; f[10] = rx.y; f[11] = rx.z;
    } else {
        #pragma unroll
        for (int k = 0; k < 12; k++) f[k] = 0.f;
    }
    float4* op = reinterpret_cast<float4*>(out + (long)idx * 12);
    op[0] = make_float4(f[0], f[1], f[2],  f[3]);
    op[1] = make_float4(f[4], f[5], f[6],  f[7]);
    op[2] = make_float4(f[8], f[9], f[10], f[11]);

    if (mask) {
        int pos = atomicAdd(&g_count, 1);
        if (pos < LIST_CAP) g_list[pos] = idx;
    }
}

// ---------------- Kernel 2: one warp per survivor, triangles across lanes ----------------
__global__ void __launch_bounds__(256) occl_kernel(
    const float* __restrict__ verts,
    const int*   __restrict__ tris,
    float*       __restrict__ out,
    int T)
{
    const int nw   = blockDim.x >> 5;
    const int lane = threadIdx.x & 31;
    const int wrp  = blockIdx.x * nw + (threadIdx.x >> 5);

    int cnt = g_count;
    if (blockIdx.x * nw >= cnt) return;   // whole block empty
    if (wrp >= cnt) return;               // warp-uniform exit

    int idx = g_list[wrp];
    float* pp = out + (long)idx * 12;

    // broadcast-load the 4 path points (all lanes read same addresses)
    float f[12];
    #pragma unroll
    for (int k = 0; k < 12; k++) f[k] = pp[k];

    V3 q0 = v3(f[0], f[1],  f[2]);   // tx
    V3 q1 = v3(f[3], f[4],  f[5]);   // p0
    V3 q2 = v3(f[6], f[7],  f[8]);   // p1
    V3 q3 = v3(f[9], f[10], f[11]);  // rx

    V3 ro[3] = { q0, q1, q2 };
    V3 rd[3] = { vsub(q1, q0), vsub(q2, q1), vsub(q3, q2) };

    bool occ = false;
    for (int t = lane; t < T; t += 32) {
        int ia = __ldg(tris + 3*t + 0), ib = __ldg(tris + 3*t + 1), ic = __ldg(tris + 3*t + 2);
        V3 w0 = ldg3(verts + 3*ia);
        V3 w1 = ldg3(verts + 3*ib);
        V3 w2 = ldg3(verts + 3*ic);
        V3 e1 = vsub(w1, w0);
        V3 e2 = vsub(w2, w0);

        #pragma unroll
        for (int r = 0; r < 3; r++) {
            V3 o  = ro[r];
            V3 dd = rd[r];
            V3 h = vcross(dd, e2);
            float a = vdot(e1, h);
            float inv = 1.0f / ((fabsf(a) < F_EPS) ? 1.0f : a);
            V3 s = vsub(o, w0);
            float u = vdot(s, h) * inv;
            V3 q = vcross(s, e1);
            float v = vdot(dd, q) * inv;
            float tp = vdot(e2, q) * inv;
            bool hit = (fabsf(a) > F_EPS) && (u >= 0.f) && (v >= 0.f)
                       && (u + v <= 1.f) && (tp > F_EPS);
            occ = occ || (hit && (tp < F_TMAX));
        }
    }
    occ = __any_sync(0xffffffffu, occ);

    if (occ && lane < 12) pp[lane] = 0.f;  // zero the occluded path, 12 lanes in parallel
}

extern "C" void kernel_launch(void* const* d_in, const int* in_sizes, int n_in,
                              void* d_out, int out_size) {
    const float* tx_g    = (const float*)d_in[0];
    const float* rx_g    = (const float*)d_in[1];
    const float* verts   = (const float*)d_in[2];
    const float* normals = (const float*)d_in[3];
    const int*   tris    = (const int*)  d_in[4];
    const int*   pc      = (const int*)  d_in[5];
    float* out = (float*)d_out;

    int ntx = in_sizes[0] / 3;
    int nrx = in_sizes[1] / 3;
    int T   = in_sizes[4] / 3;
    int P   = in_sizes[5] / 2;

    long total = (long)P * ntx * nrx;

    // reset survivor counter (graph-capturable, no allocation)
    void* cnt_ptr = nullptr;
    cudaGetSymbolAddress(&cnt_ptr, g_count);
    cudaMemsetAsync(cnt_ptr, 0, sizeof(int));

    {
        int block = 128;
        int grid  = (int)((total + block - 1) / block);
        paths_kernel<<<grid, block>>>(tx_g, rx_g, verts, normals, tris, pc,
                                      out, P, T, ntx, nrx);
    }
    {
        // worst case: every candidate survives -> one warp each
        int block = 256;
        int nw    = block / 32;
        int grid  = (int)((total + nw - 1) / nw);
        occl_kernel<<<grid, block>>>(verts, tris, out, T);
    }
}

// round 15
// speedup vs baseline: 1.0023x; 1.0023x over previous
#include <cuda_runtime.h>
#include <cuda_bf16.h>

#define F_EPS  1e-6f
#define F_TMAX 0.999f

struct V3 { float x, y, z; };

__device__ __forceinline__ V3 v3(float x, float y, float z) { V3 r; r.x=x; r.y=y; r.z=z; return r; }
__device__ __forceinline__ V3 vsub(V3 a, V3 b) { return v3(a.x-b.x, a.y-b.y, a.z-b.z); }
__device__ __forceinline__ V3 vadd(V3 a, V3 b) { return v3(a.x+b.x, a.y+b.y, a.z+b.z); }
__device__ __forceinline__ V3 vscale(V3 a, float s) { return v3(a.x*s, a.y*s, a.z*s); }
__device__ __forceinline__ float vdot(V3 a, V3 b) { return a.x*b.x + a.y*b.y + a.z*b.z; }
__device__ __forceinline__ V3 vcross(V3 a, V3 b) {
    return v3(a.y*b.z - a.z*b.y,
              a.z*b.x - a.x*b.z,
              a.x*b.y - a.y*b.x);
}
__device__ __forceinline__ V3 ldg3(const float* p) { return v3(__ldg(p), __ldg(p+1), __ldg(p+2)); }

__device__ __forceinline__ bool tri_contains(V3 a, V3 b, V3 c, V3 p) {
    V3 n0 = vcross(vsub(p, a), vsub(b, a));
    V3 n1 = vcross(vsub(p, b), vsub(c, b));
    V3 n2 = vcross(vsub(p, c), vsub(a, c));
    float d01 = vdot(n0, n1);
    float d12 = vdot(n1, n2);
    float d20 = vdot(n2, n0);
    bool pos = (d01 >= 0.f) && (d12 >= 0.f) && (d20 >= 0.f);
    bool neg = (d01 <= 0.f) && (d12 <= 0.f) && (d20 <= 0.f);
    return pos || neg;
}

// Survivor worklist (device globals — no runtime allocation).
#define LIST_CAP (1 << 16)
__device__ int g_count;
__device__ int g_list[LIST_CAP];

// ---------------- Kernel 1: image method + masks, push survivors ----------------
__global__ void __launch_bounds__(128) paths_kernel(
    const float* __restrict__ tx_g,      // [ntx,3]
    const float* __restrict__ rx_g,      // [nrx,3]
    const float* __restrict__ verts,     // [V,3]
    const float* __restrict__ normals,   // [T,3]
    const int*   __restrict__ tris,      // [T,3]
    const int*   __restrict__ pc,        // [P,2]
    float*       __restrict__ out,       // [P,ntx,nrx,4,3]
    int P, int T, int ntx, int nrx)
{
    int idx = blockIdx.x * blockDim.x + threadIdx.x;
    int pr  = ntx * nrx;
    long total = (long)P * pr;
    if (idx >= total) return;

    int p   = idx / pr;
    int rem = idx - p * pr;
    int it  = rem / nrx;
    int ir  = rem - it * nrx;

    V3 tx = ldg3(tx_g + 3*it);
    V3 rx = ldg3(rx_g + 3*ir);

    int m0 = __ldg(pc + 2*p + 0);
    int m1 = __ldg(pc + 2*p + 1);

    int ia0 = __ldg(tris + 3*m0 + 0), ib0 = __ldg(tris + 3*m0 + 1), ic0 = __ldg(tris + 3*m0 + 2);
    int ia1 = __ldg(tris + 3*m1 + 0), ib1 = __ldg(tris + 3*m1 + 1), ic1 = __ldg(tris + 3*m1 + 2);

    V3 A0 = ldg3(verts + 3*ia0), B0 = ldg3(verts + 3*ib0), C0 = ldg3(verts + 3*ic0);
    V3 A1 = ldg3(verts + 3*ia1), B1 = ldg3(verts + 3*ib1), C1 = ldg3(verts + 3*ic1);
    V3 n0 = ldg3(normals + 3*m0);
    V3 n1 = ldg3(normals + 3*m1);
    V3 v0 = A0;   // mirror_v = triangle vertex 0
    V3 v1 = A1;

    // ---- image method (order 2) ----
    V3 img0 = vsub(tx,   vscale(n0, 2.f * vdot(vsub(tx,   v0), n0)));
    V3 img1 = vsub(img0, vscale(n1, 2.f * vdot(vsub(img0, v1), n1)));

    V3 d1 = vsub(rx, img1);
    float den1 = vdot(d1, n1);
    den1 = (fabsf(den1) < F_EPS) ? F_EPS : den1;
    float t1 = vdot(vsub(v1, img1), n1) / den1;
    V3 p1 = vadd(img1, vscale(d1, t1));

    V3 d0 = vsub(p1, img0);
    float den0 = vdot(d0, n0);
    den0 = (fabsf(den0) < F_EPS) ? F_EPS : den0;
    float t0 = vdot(vsub(v0, img0), n0) / den0;
    V3 p0 = vadd(img0, vscale(d0, t0));

    // ---- containment + same-side masks ----
    bool mask = tri_contains(A0, B0, C0, p0) && tri_contains(A1, B1, C1, p1);
    if (mask) {
        float dp0 = vdot(vsub(tx, v0), n0);
        float dn0 = vdot(vsub(p1, v0), n0);
        float dp1 = vdot(vsub(p0, v1), n1);
        float dn1 = vdot(vsub(rx, v1), n1);
        mask = (dp0 * dn0 >= 0.f) && (dp1 * dn1 >= 0.f);
    }

    // ---- write tentative result; occlusion kernel zeroes the occluded ones ----
    float f[12];
    if (mask) {
        f[0] = tx.x; f[1]  = tx.y; f[2]  = tx.z;
        f[3] = p0.x; f[4]  = p0.y; f[5]  = p0.z;
        f[6] = p1.x; f[7]  = p1.y; f[8]  = p1.z;
        f[9] = rx.x; f[10] = rx.y; f[11] = rx.z;
    } else {
        #pragma unroll
        for (int k = 0; k < 12; k++) f[k] = 0.f;
    }
    float4* op = reinterpret_cast<float4*>(out + (long)idx * 12);
    op[0] = make_float4(f[0], f[1], f[2],  f[3]);
    op[1] = make_float4(f[4], f[5], f[6],  f[7]);
    op[2] = make_float4(f[8], f[9], f[10], f[11]);

    if (mask) {
        int pos = atomicAdd(&g_count, 1);
        if (pos < LIST_CAP) g_list[pos] = idx;
    }
}

// ---------------- Kernel 2: one warp per survivor, triangles across lanes ----------------
__global__ void __launch_bounds__(256) occl_kernel(
    const float* __restrict__ verts,
    const int*   __restrict__ tris,
    float*       __restrict__ out,
    int T)
{
    const int nw   = blockDim.x >> 5;
    const int lane = threadIdx.x & 31;
    const int wrp  = blockIdx.x * nw + (threadIdx.x >> 5);

    int cnt = g_count;
    if (blockIdx.x * nw >= cnt) return;   // whole block empty
    if (wrp >= cnt) return;               // warp-uniform exit

    int idx = g_list[wrp];
    float* pp = out + (long)idx * 12;

    // broadcast-load the 4 path points (all lanes read same addresses)
    float f[12];
    #pragma unroll
    for (int k = 0; k < 12; k++) f[k] = pp[k];

    V3 q0 = v3(f[0], f[1],  f[2]);   // tx
    V3 q1 = v3(f[3], f[4],  f[5]);   // p0
    V3 q2 = v3(f[6], f[7],  f[8]);   // p1
    V3 q3 = v3(f[9], f[10], f[11]);  // rx

    V3 ro[3] = { q0, q1, q2 };
    V3 rd[3] = { vsub(q1, q0), vsub(q2, q1), vsub(q3, q2) };

    bool occ = false;
    for (int t = lane; t < T; t += 32) {
        int ia = __ldg(tris + 3*t + 0), ib = __ldg(tris + 3*t + 1), ic = __ldg(tris + 3*t + 2);
        V3 w0 = ldg3(verts + 3*ia);
        V3 w1 = ldg3(verts + 3*ib);
        V3 w2 = ldg3(verts + 3*ic);
        V3 e1 = vsub(w1, w0);
        V3 e2 = vsub(w2, w0);

        #pragma unroll
        for (int r = 0; r < 3; r++) {
            V3 o  = ro[r];
            V3 dd = rd[r];
            V3 h = vcross(dd, e2);
            float a = vdot(e1, h);
            float inv = 1.0f / ((fabsf(a) < F_EPS) ? 1.0f : a);
            V3 s = vsub(o, w0);
            float u = vdot(s, h) * inv;
            V3 q = vcross(s, e1);
            float v = vdot(dd, q) * inv;
            float tp = vdot(e2, q) * inv;
            bool hit = (fabsf(a) > F_EPS) && (u >= 0.f) && (v >= 0.f)
                       && (u + v <= 1.f) && (tp > F_EPS);
            occ = occ || (hit && (tp < F_TMAX));
        }
    }
    occ = __any_sync(0xffffffffu, occ);

    if (occ && lane < 12) pp[lane] = 0.f;  // zero the occluded path, 12 lanes in parallel
}

extern "C" void kernel_launch(void* const* d_in, const int* in_sizes, int n_in,
                              void* d_out, int out_size) {
    const float* tx_g    = (const float*)d_in[0];
    const float* rx_g    = (const float*)d_in[1];
    const float* verts   = (const float*)d_in[2];
    const float* normals = (const float*)d_in[3];
    const int*   tris    = (const int*)  d_in[4];
    const int*   pc      = (const int*)  d_in[5];
    float* out = (float*)d_out;

    int ntx = in_sizes[0] / 3;
    int nrx = in_sizes[1] / 3;
    int T   = in_sizes[4] / 3;
    int P   = in_sizes[5] / 2;

    long total = (long)P * ntx * nrx;

    // reset survivor counter (graph-capturable, no allocation)
    void* cnt_ptr = nullptr;
    cudaGetSymbolAddress(&cnt_ptr, g_count);
    cudaMemsetAsync(cnt_ptr, 0, sizeof(int));

    {
        int block = 128;
        int grid  = (int)((total + block - 1) / block);
        paths_kernel<<<grid, block>>>(tx_g, rx_g, verts, normals, tris, pc,
                                      out, P, T, ntx, nrx);
    }
    {
        // worst case: every candidate survives -> one warp each
        int block = 256;
        int nw    = block / 32;
        int grid  = (int)((total + nw - 1) / nw);
        occl_kernel<<<grid, block>>>(verts, tris, out, T);
    }
}

// round 16
// speedup vs baseline: 1.1311x; 1.1285x over previous
#include <cuda_runtime.h>
#include <cuda_bf16.h>

#define F_EPS  1e-6f
#define F_TMAX 0.999f

struct V3 { float x, y, z; };

__device__ __forceinline__ V3 v3(float x, float y, float z) { V3 r; r.x=x; r.y=y; r.z=z; return r; }
__device__ __forceinline__ V3 vsub(V3 a, V3 b) { return v3(a.x-b.x, a.y-b.y, a.z-b.z); }
__device__ __forceinline__ V3 vadd(V3 a, V3 b) { return v3(a.x+b.x, a.y+b.y, a.z+b.z); }
__device__ __forceinline__ V3 vscale(V3 a, float s) { return v3(a.x*s, a.y*s, a.z*s); }
__device__ __forceinline__ float vdot(V3 a, V3 b) { return a.x*b.x + a.y*b.y + a.z*b.z; }
__device__ __forceinline__ V3 vcross(V3 a, V3 b) {
    return v3(a.y*b.z - a.z*b.y,
              a.z*b.x - a.x*b.z,
              a.x*b.y - a.y*b.x);
}
__device__ __forceinline__ V3 ldg3(const float* p) { return v3(__ldg(p), __ldg(p+1), __ldg(p+2)); }

__device__ __forceinline__ bool tri_contains(V3 a, V3 b, V3 c, V3 p) {
    V3 n0 = vcross(vsub(p, a), vsub(b, a));
    V3 n1 = vcross(vsub(p, b), vsub(c, b));
    V3 n2 = vcross(vsub(p, c), vsub(a, c));
    float d01 = vdot(n0, n1);
    float d12 = vdot(n1, n2);
    float d20 = vdot(n2, n0);
    bool pos = (d01 >= 0.f) && (d12 >= 0.f) && (d20 >= 0.f);
    bool neg = (d01 <= 0.f) && (d12 <= 0.f) && (d20 <= 0.f);
    return pos || neg;
}

// Survivor worklist (device globals — no runtime allocation).
#define LIST_CAP (1 << 16)
__device__ int g_count;
__device__ int g_list[LIST_CAP];

// ---------------- Kernel 1: image method + masks, push survivors ----------------
__global__ void __launch_bounds__(128) paths_kernel(
    const float* __restrict__ tx_g,      // [ntx,3]
    const float* __restrict__ rx_g,      // [nrx,3]
    const float* __restrict__ verts,     // [V,3]
    const float* __restrict__ normals,   // [T,3]
    const int*   __restrict__ tris,      // [T,3]
    const int*   __restrict__ pc,        // [P,2]
    float*       __restrict__ out,       // [P,ntx,nrx,4,3]
    int P, int T, int ntx, int nrx)
{
    int idx = blockIdx.x * blockDim.x + threadIdx.x;
    int pr  = ntx * nrx;
    long total = (long)P * pr;
    if (idx >= total) return;

    int p   = idx / pr;
    int rem = idx - p * pr;
    int it  = rem / nrx;
    int ir  = rem - it * nrx;

    V3 tx = ldg3(tx_g + 3*it);
    V3 rx = ldg3(rx_g + 3*ir);

    int m0 = __ldg(pc + 2*p + 0);
    int m1 = __ldg(pc + 2*p + 1);

    int ia0 = __ldg(tris + 3*m0 + 0), ib0 = __ldg(tris + 3*m0 + 1), ic0 = __ldg(tris + 3*m0 + 2);
    int ia1 = __ldg(tris + 3*m1 + 0), ib1 = __ldg(tris + 3*m1 + 1), ic1 = __ldg(tris + 3*m1 + 2);

    V3 A0 = ldg3(verts + 3*ia0), B0 = ldg3(verts + 3*ib0), C0 = ldg3(verts + 3*ic0);
    V3 A1 = ldg3(verts + 3*ia1), B1 = ldg3(verts + 3*ib1), C1 = ldg3(verts + 3*ic1);
    V3 n0 = ldg3(normals + 3*m0);
    V3 n1 = ldg3(normals + 3*m1);
    V3 v0 = A0;   // mirror_v = triangle vertex 0
    V3 v1 = A1;

    // ---- image method (order 2) ----
    V3 img0 = vsub(tx,   vscale(n0, 2.f * vdot(vsub(tx,   v0), n0)));
    V3 img1 = vsub(img0, vscale(n1, 2.f * vdot(vsub(img0, v1), n1)));

    V3 d1 = vsub(rx, img1);
    float den1 = vdot(d1, n1);
    den1 = (fabsf(den1) < F_EPS) ? F_EPS : den1;
    float t1 = vdot(vsub(v1, img1), n1) / den1;
    V3 p1 = vadd(img1, vscale(d1, t1));

    V3 d0 = vsub(p1, img0);
    float den0 = vdot(d0, n0);
    den0 = (fabsf(den0) < F_EPS) ? F_EPS : den0;
    float t0 = vdot(vsub(v0, img0), n0) / den0;
    V3 p0 = vadd(img0, vscale(d0, t0));

    // ---- containment + same-side masks ----
    bool mask = tri_contains(A0, B0, C0, p0) && tri_contains(A1, B1, C1, p1);
    if (mask) {
        float dp0 = vdot(vsub(tx, v0), n0);
        float dn0 = vdot(vsub(p1, v0), n0);
        float dp1 = vdot(vsub(p0, v1), n1);
        float dn1 = vdot(vsub(rx, v1), n1);
        mask = (dp0 * dn0 >= 0.f) && (dp1 * dn1 >= 0.f);
    }

    // ---- write tentative result; occlusion kernel zeroes the occluded ones ----
    float f[12];
    if (mask) {
        f[0] = tx.x; f[1]  = tx.y; f[2]  = tx.z;
        f[3] = p0.x; f[4]  = p0.y; f[5]  = p0.z;
        f[6] = p1.x; f[7]  = p1.y; f[8]  = p1.z;
        f[9] = rx.x; f[10] = rx.y; f[11] = rx.z;
    } else {
        #pragma unroll
        for (int k = 0; k < 12; k++) f[k] = 0.f;
    }
    float4* op = reinterpret_cast<float4*>(out + (long)idx * 12);
    op[0] = make_float4(f[0], f[1], f[2],  f[3]);
    op[1] = make_float4(f[4], f[5], f[6],  f[7]);
    op[2] = make_float4(f[8], f[9], f[10], f[11]);

    if (mask) {
        int pos = atomicAdd(&g_count, 1);
        if (pos < LIST_CAP) g_list[pos] = idx;
    }
}

// ---------------- Kernel 2: one warp per survivor, triangles across lanes ----------------
__global__ void __launch_bounds__(256) occl_kernel(
    const float* __restrict__ verts,
    const int*   __restrict__ tris,
    float*       __restrict__ out,
    int T)
{
    const int nw   = blockDim.x >> 5;
    const int lane = threadIdx.x & 31;
    const int wrp  = blockIdx.x * nw + (threadIdx.x >> 5);

    int cnt = g_count;
    if (blockIdx.x * nw >= cnt) return;   // whole block empty
    if (wrp >= cnt) return;               // warp-uniform exit

    int idx = g_list[wrp];
    float* pp = out + (long)idx * 12;

    // broadcast-load the 4 path points (all lanes read same addresses)
    float f[12];
    #pragma unroll
    for (int k = 0; k < 12; k++) f[k] = pp[k];

    V3 q0 = v3(f[0], f[1],  f[2]);   // tx
    V3 q1 = v3(f[3], f[4],  f[5]);   // p0
    V3 q2 = v3(f[6], f[7],  f[8]);   // p1
    V3 q3 = v3(f[9], f[10], f[11]);  // rx

    V3 ro[3] = { q0, q1, q2 };
    V3 rd[3] = { vsub(q1, q0), vsub(q2, q1), vsub(q3, q2) };

    bool occ = false;
    for (int t = lane; t < T; t += 32) {
        int ia = __ldg(tris + 3*t + 0), ib = __ldg(tris + 3*t + 1), ic = __ldg(tris + 3*t + 2);
        V3 w0 = ldg3(verts + 3*ia);
        V3 w1 = ldg3(verts + 3*ib);
        V3 w2 = ldg3(verts + 3*ic);
        V3 e1 = vsub(w1, w0);
        V3 e2 = vsub(w2, w0);

        #pragma unroll
        for (int r = 0; r < 3; r++) {
            V3 o  = ro[r];
            V3 dd = rd[r];
            V3 h = vcross(dd, e2);
            float a = vdot(e1, h);
            float inv = 1.0f / ((fabsf(a) < F_EPS) ? 1.0f : a);
            V3 s = vsub(o, w0);
            float u = vdot(s, h) * inv;
            V3 q = vcross(s, e1);
            float v = vdot(dd, q) * inv;
            float tp = vdot(e2, q) * inv;
            bool hit = (fabsf(a) > F_EPS) && (u >= 0.f) && (v >= 0.f)
                       && (u + v <= 1.f) && (tp > F_EPS);
            occ = occ || (hit && (tp < F_TMAX));
        }
    }
    occ = __any_sync(0xffffffffu, occ);

    if (occ && lane < 12) pp[lane] = 0.f;  // zero the occluded path, 12 lanes in parallel
}

extern "C" void kernel_launch(void* const* d_in, const int* in_sizes, int n_in,
                              void* d_out, int out_size) {
    const float* tx_g    = (const float*)d_in[0];
    const float* rx_g    = (const float*)d_in[1];
    const float* verts   = (const float*)d_in[2];
    const float* normals = (const float*)d_in[3];
    const int*   tris    = (const int*)  d_in[4];
    const int*   pc      = (const int*)  d_in[5];
    float* out = (float*)d_out;

    int ntx = in_sizes[0] / 3;
    int nrx = in_sizes[1] / 3;
    int T   = in_sizes[4] / 3;
    int P   = in_sizes[5] / 2;

    long total = (long)P * ntx * nrx;

    // reset survivor counter (graph-capturable, no allocation)
    void* cnt_ptr = nullptr;
    cudaGetSymbolAddress(&cnt_ptr, g_count);
    cudaMemsetAsync(cnt_ptr, 0, sizeof(int));

    {
        int block = 128;
        int grid  = (int)((total + block - 1) / block);
        paths_kernel<<<grid, block>>>(tx_g, rx_g, verts, normals, tris, pc,
                                      out, P, T, ntx, nrx);
    }
    {
        // worst case: every candidate survives -> one warp each
        int block = 256;
        int nw    = block / 32;
        int grid  = (int)((total + nw - 1) / nw);
        occl_kernel<<<grid, block>>>(verts, tris, out, T);
    }
}